// round 1
// baseline (speedup 1.0000x reference)
#include <cuda_runtime.h>
#include <cuda_bf16.h>
#include <math.h>

// Problem dims
#define B_   64
#define DV_  2048
#define WH_  196
#define DQ_  2400
#define DA_  1200
#define G_   2
#define DH_  1200
#define NC_  3000
#define MROWS (B_*WH_)   // 12544

// ---------------- scratch (device globals; no allocation allowed) ----------
__device__ float g_xatt[MROWS * DA_];        // [B*196, 1200]  ~60 MB
__device__ float g_xq  [B_ * DA_];           // [64, 1200]
__device__ float g_att [B_ * G_ * WH_];      // [64, 2, 196]
__device__ float g_vatt[B_ * G_ * DV_];      // [64, 2, 2048]
__device__ float g_vfus[B_ * G_ * DH_];      // [64, 2400]
__device__ float g_qfus[B_ * G_ * DH_];      // [64, 2400]

// ---------------------------------------------------------------------------
// Big tiled GEMM: 128x128 tile, BK=16, 256 threads, 8x8 per thread.
// MODE 0: A[m,k] = input_v[b, k, nsp] where m=(b,nsp); epilogue
//         C = tanh( tanh(acc + bias[n]) * xq[b, n] )
// ---------------------------------------------------------------------------
template<int MODE>
__global__ void gemm128(const float* __restrict__ A,
                        const float* __restrict__ W,
                        const float* __restrict__ bias,
                        const float* __restrict__ extra,
                        float* __restrict__ C,
                        int M, int N, int K, int lda, int ldc)
{
    __shared__ float As[16][128];
    __shared__ float Bs[16][128];

    const int tid = threadIdx.x;           // 0..255
    const int ty  = tid >> 4;              // 0..15
    const int tx  = tid & 15;              // 0..15
    const int m0  = blockIdx.y * 128;
    const int n0  = blockIdx.x * 128;

    float acc[8][8];
#pragma unroll
    for (int i = 0; i < 8; i++)
#pragma unroll
        for (int j = 0; j < 8; j++) acc[i][j] = 0.f;

    for (int k0 = 0; k0 < K; k0 += 16) {
        // load A tile -> As[k][m]  (m fastest across threads: coalesced for MODE0)
#pragma unroll
        for (int i = 0; i < 8; i++) {
            int e = i * 256 + tid;
            int m = e & 127, k = e >> 7;
            int mg = m0 + m;
            float v = 0.f;
            if (mg < M) {
                if (MODE == 0) {
                    int b  = mg / WH_;
                    int ns = mg - b * WH_;
                    v = A[((long)b * K + (k0 + k)) * WH_ + ns];
                } else {
                    v = A[(long)mg * lda + k0 + k];
                }
            }
            As[k][m] = v;
        }
        // load W tile -> Bs[k][n], W is [N,K] row-major (k contiguous)
#pragma unroll
        for (int i = 0; i < 8; i++) {
            int e = i * 256 + tid;
            int k = e & 15, n = e >> 4;
            int ng = n0 + n;
            Bs[k][n] = (ng < N) ? W[(long)ng * K + k0 + k] : 0.f;
        }
        __syncthreads();

#pragma unroll
        for (int kk = 0; kk < 16; kk++) {
            float a[8], b[8];
#pragma unroll
            for (int i = 0; i < 8; i++) a[i] = As[kk][ty * 8 + i];
#pragma unroll
            for (int j = 0; j < 8; j++) b[j] = Bs[kk][tx * 8 + j];
#pragma unroll
            for (int i = 0; i < 8; i++)
#pragma unroll
                for (int j = 0; j < 8; j++) acc[i][j] += a[i] * b[j];
        }
        __syncthreads();
    }

#pragma unroll
    for (int i = 0; i < 8; i++) {
        int mg = m0 + ty * 8 + i;
        if (mg >= M) continue;
#pragma unroll
        for (int j = 0; j < 8; j++) {
            int n = n0 + tx * 8 + j;
            if (n >= N) continue;
            float v = acc[i][j] + bias[n];
            if (MODE == 0) {
                int b = mg / WH_;
                float t1 = tanhf(v);
                C[(long)mg * ldc + n] = tanhf(t1 * extra[b * N + n]);
            } else {
                C[(long)mg * ldc + n] = tanhf(v);
            }
        }
    }
}

// ---------------------------------------------------------------------------
// Small tiled GEMM: 64x64 tile, BK=16, 256 threads, 4x4 per thread.
// Batched over blockIdx.z via element strides (for the 2 glimpses).
// MODE 1: C = tanh(acc + bias[n]);  MODE 2: A[m,k]=A*extra elementwise, C=acc+bias
// ---------------------------------------------------------------------------
template<int MODE>
__global__ void gemm64(const float* __restrict__ A,
                       const float* __restrict__ W,
                       const float* __restrict__ bias,
                       const float* __restrict__ extra,
                       float* __restrict__ C,
                       int M, int N, int K, int lda, int ldc,
                       long aBS, long wBS, long bBS, long cBS)
{
    const int g = blockIdx.z;
    A    += (long)g * aBS;
    W    += (long)g * wBS;
    bias += (long)g * bBS;
    C    += (long)g * cBS;

    __shared__ float As[16][64];
    __shared__ float Bs[16][64];

    const int tid = threadIdx.x;
    const int ty  = tid >> 4;      // 0..15
    const int tx  = tid & 15;      // 0..15
    const int m0  = blockIdx.y * 64;
    const int n0  = blockIdx.x * 64;

    float acc[4][4];
#pragma unroll
    for (int i = 0; i < 4; i++)
#pragma unroll
        for (int j = 0; j < 4; j++) acc[i][j] = 0.f;

    for (int k0 = 0; k0 < K; k0 += 16) {
#pragma unroll
        for (int i = 0; i < 4; i++) {
            int e = i * 256 + tid;
            int m = e & 63, k = e >> 6;
            int mg = m0 + m;
            float v = 0.f;
            if (mg < M) {
                long idx = (long)mg * lda + k0 + k;
                v = A[idx];
                if (MODE == 2) v *= extra[idx];
            }
            As[k][m] = v;
        }
#pragma unroll
        for (int i = 0; i < 4; i++) {
            int e = i * 256 + tid;
            int k = e & 15, n = e >> 4;
            int ng = n0 + n;
            Bs[k][n] = (ng < N) ? W[(long)ng * K + k0 + k] : 0.f;
        }
        __syncthreads();

#pragma unroll
        for (int kk = 0; kk < 16; kk++) {
            float a[4], b[4];
#pragma unroll
            for (int i = 0; i < 4; i++) a[i] = As[kk][ty * 4 + i];
#pragma unroll
            for (int j = 0; j < 4; j++) b[j] = Bs[kk][tx * 4 + j];
#pragma unroll
            for (int i = 0; i < 4; i++)
#pragma unroll
                for (int j = 0; j < 4; j++) acc[i][j] += a[i] * b[j];
        }
        __syncthreads();
    }

#pragma unroll
    for (int i = 0; i < 4; i++) {
        int mg = m0 + ty * 4 + i;
        if (mg >= M) continue;
#pragma unroll
        for (int j = 0; j < 4; j++) {
            int n = n0 + tx * 4 + j;
            if (n >= N) continue;
            float v = acc[i][j] + bias[n];
            C[(long)mg * ldc + n] = (MODE == 1) ? tanhf(v) : v;
        }
    }
}

// ---------------------------------------------------------------------------
// wgt[b,g,n] = sum_d xatt[b,n,d] * Watt[g,d] + batt[g]   (one warp per (b,n))
// ---------------------------------------------------------------------------
__global__ void wgt_kernel(const float* __restrict__ xatt,
                           const float* __restrict__ Watt,
                           const float* __restrict__ batt,
                           float* __restrict__ out)
{
    int w    = (blockIdx.x * blockDim.x + threadIdx.x) >> 5;
    int lane = threadIdx.x & 31;
    if (w >= MROWS) return;
    int b = w / WH_, n = w - b * WH_;
    const float* xr = xatt + (long)w * DA_;
    float s0 = 0.f, s1 = 0.f;
    for (int d = lane; d < DA_; d += 32) {
        float x = xr[d];
        s0 += x * Watt[d];
        s1 += x * Watt[DA_ + d];
    }
#pragma unroll
    for (int o = 16; o > 0; o >>= 1) {
        s0 += __shfl_down_sync(0xffffffffu, s0, o);
        s1 += __shfl_down_sync(0xffffffffu, s1, o);
    }
    if (lane == 0) {
        out[((long)b * G_ + 0) * WH_ + n] = s0 + batt[0];
        out[((long)b * G_ + 1) * WH_ + n] = s1 + batt[1];
    }
}

// softmax over 196 per (b,g)
__global__ void softmax196(const float* __restrict__ wgt, float* __restrict__ att)
{
    __shared__ float red[256];
    int bg = blockIdx.x;          // 0..127
    int t  = threadIdx.x;         // 0..255
    const float* in = wgt + (long)bg * WH_;
    float v = (t < WH_) ? in[t] : -1e30f;
    red[t] = v; __syncthreads();
    for (int s = 128; s > 0; s >>= 1) {
        if (t < s) red[t] = fmaxf(red[t], red[t + s]);
        __syncthreads();
    }
    float mx = red[0]; __syncthreads();
    float e = (t < WH_) ? expf(v - mx) : 0.f;
    red[t] = e; __syncthreads();
    for (int s = 128; s > 0; s >>= 1) {
        if (t < s) red[t] += red[t + s];
        __syncthreads();
    }
    float inv = 1.f / red[0];
    if (t < WH_) att[(long)bg * WH_ + t] = e * inv;
}

// v_att[b,g,d] = sum_n att[b,g,n] * input_v[b,d,n]
// block = 256 threads = (32 lanes) x (8 d); grid = (B, DV/8)
__global__ void vatt_kernel(const float* __restrict__ v,
                            const float* __restrict__ att,
                            float* __restrict__ vatt)
{
    __shared__ float a0[WH_], a1[WH_];
    int b = blockIdx.x;
    int t = threadIdx.x;
    if (t < WH_) {
        a0[t] = att[((long)b * G_ + 0) * WH_ + t];
        a1[t] = att[((long)b * G_ + 1) * WH_ + t];
    }
    __syncthreads();
    int lane = t & 31, dd = t >> 5;
    int d = blockIdx.y * 8 + dd;
    const float* row = v + ((long)b * DV_ + d) * WH_;
    float s0 = 0.f, s1 = 0.f;
    for (int n = lane; n < WH_; n += 32) {
        float x = row[n];
        s0 += x * a0[n];
        s1 += x * a1[n];
    }
#pragma unroll
    for (int o = 16; o > 0; o >>= 1) {
        s0 += __shfl_down_sync(0xffffffffu, s0, o);
        s1 += __shfl_down_sync(0xffffffffu, s1, o);
    }
    if (lane == 0) {
        vatt[((long)b * G_ + 0) * DV_ + d] = s0;
        vatt[((long)b * G_ + 1) * DV_ + d] = s1;
    }
}

// ---------------------------------------------------------------------------
extern "C" void kernel_launch(void* const* d_in, const int* in_sizes, int n_in,
                              void* d_out, int out_size)
{
    const float* input_q = (const float*)d_in[0];
    const float* input_v = (const float*)d_in[1];
    const float* Wv_att  = (const float*)d_in[2];
    const float* bv_att  = (const float*)d_in[3];
    const float* Wq_att  = (const float*)d_in[4];
    const float* bq_att  = (const float*)d_in[5];
    const float* Watt    = (const float*)d_in[6];
    const float* batt    = (const float*)d_in[7];
    const float* Wv_fus  = (const float*)d_in[8];
    const float* bv_fus  = (const float*)d_in[9];
    const float* Wq_fus  = (const float*)d_in[10];
    const float* bq_fus  = (const float*)d_in[11];
    const float* Wc      = (const float*)d_in[12];
    const float* bc      = (const float*)d_in[13];

    float* out     = (float*)d_out;
    float* wgt_out = out + B_ * NC_;   // wgt tail of output tuple

    float *xatt, *xq, *att, *vatt, *vfus, *qfus;
    cudaGetSymbolAddress((void**)&xatt, g_xatt);
    cudaGetSymbolAddress((void**)&xq,   g_xq);
    cudaGetSymbolAddress((void**)&att,  g_att);
    cudaGetSymbolAddress((void**)&vatt, g_vatt);
    cudaGetSymbolAddress((void**)&vfus, g_vfus);
    cudaGetSymbolAddress((void**)&qfus, g_qfus);

    // 1) xq = tanh(input_q @ Wq_att^T + bq_att)          [64, 1200]
    gemm64<1><<<dim3((DA_ + 63) / 64, 1, 1), 256>>>(
        input_q, Wq_att, bq_att, nullptr, xq,
        B_, DA_, DQ_, DQ_, DA_, 0, 0, 0, 0);

    // 2) xatt = tanh( tanh(V^T Wv_att^T + b) * xq )      [12544, 1200]
    gemm128<0><<<dim3((DA_ + 127) / 128, MROWS / 128), 256>>>(
        input_v, Wv_att, bv_att, xq, xatt,
        MROWS, DA_, DV_, 0, DA_);

    // 3) wgt (also part of output)                       [64, 2, 196]
    wgt_kernel<<<(MROWS * 32 + 255) / 256, 256>>>(xatt, Watt, batt, wgt_out);

    // 4) att = softmax(wgt, axis=n)
    softmax196<<<B_ * G_, 256>>>(wgt_out, att);

    // 5) v_att = att @ V                                 [64, 2, 2048]
    vatt_kernel<<<dim3(B_, DV_ / 8), 256>>>(input_v, att, vatt);

    // 6) v_fus = tanh(v_att @ Wv_fus^T + b)  batched g   -> [64, 2400]
    gemm64<1><<<dim3((DH_ + 63) / 64, 1, G_), 256>>>(
        vatt, Wv_fus, bv_fus, nullptr, vfus,
        B_, DH_, DV_, G_ * DV_, G_ * DH_,
        (long)DV_, (long)DH_ * DV_, (long)DH_, (long)DH_);

    // 7) q_fus = tanh(input_q @ Wq_fus^T + b)            [64, 2400]
    gemm64<1><<<dim3((G_ * DH_ + 63) / 64, 1, 1), 256>>>(
        input_q, Wq_fus, bq_fus, nullptr, qfus,
        B_, G_ * DH_, DQ_, DQ_, G_ * DH_, 0, 0, 0, 0);

    // 8) x = (v_fus * q_fus) @ Wc^T + bc                 [64, 3000]
    gemm64<2><<<dim3((NC_ + 63) / 64, 1, 1), 256>>>(
        vfus, Wc, bc, qfus, out,
        B_, NC_, G_ * DH_, G_ * DH_, NC_, 0, 0, 0, 0);
}